// round 14
// baseline (speedup 1.0000x reference)
#include <cuda_runtime.h>
#include <cstdint>
#include <cstddef>

#define NN 100000
#define NE 640000
#define IN_CH 128
#define HID 256
#define OC 64
#define SW 40   // smem row stride in words (mod 32 == 8 -> conflict-free LDS.64 frags)

// ---------------- scratch ----------------
__device__ __align__(16) float g_cnt[NN];
__device__ __align__(16) float g_agg1[(size_t)NN * IN_CH];
__device__ __align__(16) float g_h[(size_t)NN * HID];
__device__ __align__(16) float g_P[(size_t)NN * OC];
__device__ __align__(16) float g_agg2[(size_t)NN * OC];

__device__ __forceinline__ int clampN(int v) {
    return ((unsigned)v < (unsigned)NN) ? v : 0;
}

// ---------------- tf32 helpers ----------------
__device__ __forceinline__ unsigned cvt_tf32(float f) {
    unsigned r;
    asm("cvt.rna.tf32.f32 %0, %1;" : "=r"(r) : "f"(f));
    return r;
}
__device__ __forceinline__ void mma_tf32(float* c, const unsigned* a, const unsigned* b) {
    asm volatile(
        "mma.sync.aligned.m16n8k8.row.col.f32.tf32.tf32.f32 "
        "{%0,%1,%2,%3}, {%4,%5,%6,%7}, {%8,%9}, {%0,%1,%2,%3};"
        : "+f"(c[0]), "+f"(c[1]), "+f"(c[2]), "+f"(c[3])
        : "r"(a[0]), "r"(a[1]), "r"(a[2]), "r"(a[3]), "r"(b[0]), "r"(b[1]));
}

// pair-packed store: within each 8-k group order {v0,v4,v1,v5,v2,v6,v3,v7}
// so fragment pair (k, k+4) is one 8-byte word -> LDS.64 fragment loads.
__device__ __forceinline__ void store_packed16(unsigned* rowptr, int lc,
                                               const float4* v4, float s) {
    unsigned t[16];
#pragma unroll
    for (int i = 0; i < 4; i++) {
        t[i * 4 + 0] = cvt_tf32(v4[i].x * s);
        t[i * 4 + 1] = cvt_tf32(v4[i].y * s);
        t[i * 4 + 2] = cvt_tf32(v4[i].z * s);
        t[i * 4 + 3] = cvt_tf32(v4[i].w * s);
    }
#pragma unroll
    for (int g = 0; g < 2; g++) {
        const unsigned* u = t + g * 8;
        uint4 w0 = make_uint4(u[0], u[4], u[1], u[5]);
        uint4 w1 = make_uint4(u[2], u[6], u[3], u[7]);
        *(uint4*)(rowptr + lc + g * 8)     = w0;
        *(uint4*)(rowptr + lc + g * 8 + 4) = w1;
    }
}

// ---------------- degree count + inverse ----------------
__global__ void count_kernel(const int* __restrict__ ei) {
    int e = blockIdx.x * blockDim.x + threadIdx.x;
    if (e < NE) atomicAdd(&g_cnt[clampN(ei[NE + e])], 1.0f);
}
__global__ void inv_kernel() {
    int i = blockIdx.x * blockDim.x + threadIdx.x;
    if (i < NN) g_cnt[i] = 1.0f / fmaxf(g_cnt[i], 1.0f);
}

// ---------------- scatters (vector RED) ----------------
__global__ void scatter1_kernel(const int* __restrict__ ei,
                                const float* __restrict__ x) {
    constexpr int Q = IN_CH / 4;
    int gt = blockIdx.x * blockDim.x + threadIdx.x;
    int e = gt >> 5;
    int q = gt & 31;
    if (e >= NE) return;
    int s = clampN(ei[e]);
    int d = clampN(ei[NE + e]);
    float4 v = *((const float4*)x + (size_t)s * Q + q);
    atomicAdd((float4*)g_agg1 + (size_t)d * Q + q, v);
}
__global__ void scatter2_kernel(const int* __restrict__ ei) {
    constexpr int Q = OC / 4;
    int gt = blockIdx.x * blockDim.x + threadIdx.x;
    int e = gt >> 4;
    int q = gt & 15;
    if (e >= NE) return;
    int s = clampN(ei[e]);
    int d = clampN(ei[NE + e]);
    float4 v = *((const float4*)g_P + (size_t)s * Q + q);
    atomicAdd((float4*)g_agg2 + (size_t)d * Q + q, v);
}

// ---------------- layer-1 half GEMM (K=128) ----------------
// phase 0: g_h[n,c] = x[n,:].W1r[c,:] + b1[c]                    (raw, no relu)
// phase 1: g_h[n,c] = relu( (g_agg1*inv)[n,:].W1l[c,:] + g_h[n,c] )
// A source selected IN DEVICE CODE (never pass __device__ symbols from host).
__global__ void __launch_bounds__(256, 2)
gemm1_half(const float* __restrict__ x,
           const float* __restrict__ B,
           const float* __restrict__ b1,
           int phase) {
    __shared__ __align__(16) unsigned As[128][SW];
    __shared__ __align__(16) unsigned Bs[128][SW];

    const int tid = threadIdx.x;
    const int lane = tid & 31;
    const int warp = tid >> 5;
    const int wm = warp >> 1;
    const int wn = warp & 1;
    const int rowBase = blockIdx.x * 128;
    const int colBase = blockIdx.y * 128;

    const int lr = tid >> 1;
    const int lc = (tid & 1) * 16;

    int nA = rowBase + lr; if (nA >= NN) nA = NN - 1;
    const float* Araw = phase ? g_agg1 : x;      // device-side symbol resolve
    const float s = phase ? g_cnt[nA] : 1.0f;

    float acc[2][8][4];
#pragma unroll
    for (int mi = 0; mi < 2; mi++)
#pragma unroll
        for (int ni = 0; ni < 8; ni++)
#pragma unroll
            for (int t = 0; t < 4; t++) acc[mi][ni][t] = 0.0f;

#pragma unroll 1
    for (int kt = 0; kt < 4; kt++) {
        const int koff = kt * 32;
        const float* ap = Araw + (size_t)nA * IN_CH + koff + lc;
        const float* bp = B + (size_t)(colBase + lr) * IN_CH + koff + lc;

        float4 va[4], vb[4];
#pragma unroll
        for (int i = 0; i < 4; i++) va[i] = *(const float4*)(ap + i * 4);
#pragma unroll
        for (int i = 0; i < 4; i++) vb[i] = *(const float4*)(bp + i * 4);
        store_packed16(As[lr], lc, va, s);
        store_packed16(Bs[lr], lc, vb, 1.0f);
        __syncthreads();

#pragma unroll
        for (int kk = 0; kk < 4; kk++) {
            const int kc2 = kk * 8 + (lane & 3) * 2;
            unsigned a[2][4];
#pragma unroll
            for (int mi = 0; mi < 2; mi++) {
                int r0 = wm * 32 + mi * 16 + (lane >> 2);
                uint2 lo = *(const uint2*)&As[r0][kc2];
                uint2 hi = *(const uint2*)&As[r0 + 8][kc2];
                a[mi][0] = lo.x; a[mi][1] = hi.x; a[mi][2] = lo.y; a[mi][3] = hi.y;
            }
            unsigned bf[8][2];
#pragma unroll
            for (int ni = 0; ni < 8; ni++) {
                int c0 = wn * 64 + ni * 8 + (lane >> 2);
                uint2 bb = *(const uint2*)&Bs[c0][kc2];
                bf[ni][0] = bb.x; bf[ni][1] = bb.y;
            }
#pragma unroll
            for (int mi = 0; mi < 2; mi++)
#pragma unroll
                for (int ni = 0; ni < 8; ni++)
                    mma_tf32(acc[mi][ni], a[mi], bf[ni]);
        }
        __syncthreads();
    }

#pragma unroll
    for (int mi = 0; mi < 2; mi++) {
        int r0 = rowBase + wm * 32 + mi * 16 + (lane >> 2);
#pragma unroll
        for (int ni = 0; ni < 8; ni++) {
            int c = colBase + wn * 64 + ni * 8 + 2 * (lane & 3);
            if (phase == 0) {
                float bb0 = b1[c], bb1 = b1[c + 1];
                if (r0 < NN) {
                    float2 st;
                    st.x = acc[mi][ni][0] + bb0;
                    st.y = acc[mi][ni][1] + bb1;
                    *(float2*)&g_h[(size_t)r0 * HID + c] = st;
                }
                int r1 = r0 + 8;
                if (r1 < NN) {
                    float2 st;
                    st.x = acc[mi][ni][2] + bb0;
                    st.y = acc[mi][ni][3] + bb1;
                    *(float2*)&g_h[(size_t)r1 * HID + c] = st;
                }
            } else {
                if (r0 < NN) {
                    float2 pv = *(const float2*)&g_h[(size_t)r0 * HID + c];
                    float2 st;
                    st.x = fmaxf(acc[mi][ni][0] + pv.x, 0.0f);
                    st.y = fmaxf(acc[mi][ni][1] + pv.y, 0.0f);
                    *(float2*)&g_h[(size_t)r0 * HID + c] = st;
                }
                int r1 = r0 + 8;
                if (r1 < NN) {
                    float2 pv = *(const float2*)&g_h[(size_t)r1 * HID + c];
                    float2 st;
                    st.x = fmaxf(acc[mi][ni][2] + pv.x, 0.0f);
                    st.y = fmaxf(acc[mi][ni][3] + pv.y, 0.0f);
                    *(float2*)&g_h[(size_t)r1 * HID + c] = st;
                }
            }
        }
    }
}

// ---------------- layer-2 GEMM: C = h @ W^T (K=256, N=64) ----------------
// toP != 0 -> C = g_P ; else C = outRaw.
__global__ void __launch_bounds__(256, 2)
gemm2_half(const float* __restrict__ W,
           float* __restrict__ outRaw,
           int toP) {
    __shared__ __align__(16) unsigned As[128][SW];
    __shared__ __align__(16) unsigned Bs[64][SW];

    float* C = toP ? g_P : outRaw;

    const int tid = threadIdx.x;
    const int lane = tid & 31;
    const int warp = tid >> 5;
    const int wm = warp >> 1;
    const int wn = warp & 1;
    const int rowBase = blockIdx.x * 128;

    const int lr = tid >> 1;
    const int lc = (tid & 1) * 16;
    const int br = tid >> 2;
    const int bc = (tid & 3) * 8;

    int nA = rowBase + lr; if (nA >= NN) nA = NN - 1;

    float acc[2][4][4];
#pragma unroll
    for (int mi = 0; mi < 2; mi++)
#pragma unroll
        for (int ni = 0; ni < 4; ni++)
#pragma unroll
            for (int t = 0; t < 4; t++) acc[mi][ni][t] = 0.0f;

#pragma unroll 1
    for (int kt = 0; kt < 8; kt++) {
        const int koff = kt * 32;
        const float* ap = g_h + (size_t)nA * HID + koff + lc;
        float4 va[4];
#pragma unroll
        for (int i = 0; i < 4; i++) va[i] = *(const float4*)(ap + i * 4);
        store_packed16(As[lr], lc, va, 1.0f);
        {
            const float* bp = W + (size_t)br * HID + koff + bc;
            float4 v0 = *(const float4*)(bp);
            float4 v1 = *(const float4*)(bp + 4);
            unsigned u[8];
            u[0] = cvt_tf32(v0.x); u[1] = cvt_tf32(v0.y);
            u[2] = cvt_tf32(v0.z); u[3] = cvt_tf32(v0.w);
            u[4] = cvt_tf32(v1.x); u[5] = cvt_tf32(v1.y);
            u[6] = cvt_tf32(v1.z); u[7] = cvt_tf32(v1.w);
            uint4 w0 = make_uint4(u[0], u[4], u[1], u[5]);
            uint4 w1 = make_uint4(u[2], u[6], u[3], u[7]);
            *(uint4*)(Bs[br] + bc)     = w0;
            *(uint4*)(Bs[br] + bc + 4) = w1;
        }
        __syncthreads();

#pragma unroll
        for (int kk = 0; kk < 4; kk++) {
            const int kc2 = kk * 8 + (lane & 3) * 2;
            unsigned a[2][4];
#pragma unroll
            for (int mi = 0; mi < 2; mi++) {
                int r0 = wm * 32 + mi * 16 + (lane >> 2);
                uint2 lo = *(const uint2*)&As[r0][kc2];
                uint2 hi = *(const uint2*)&As[r0 + 8][kc2];
                a[mi][0] = lo.x; a[mi][1] = hi.x; a[mi][2] = lo.y; a[mi][3] = hi.y;
            }
            unsigned bf[4][2];
#pragma unroll
            for (int ni = 0; ni < 4; ni++) {
                int c0 = wn * 32 + ni * 8 + (lane >> 2);
                uint2 bb = *(const uint2*)&Bs[c0][kc2];
                bf[ni][0] = bb.x; bf[ni][1] = bb.y;
            }
#pragma unroll
            for (int mi = 0; mi < 2; mi++)
#pragma unroll
                for (int ni = 0; ni < 4; ni++)
                    mma_tf32(acc[mi][ni], a[mi], bf[ni]);
        }
        __syncthreads();
    }

#pragma unroll
    for (int mi = 0; mi < 2; mi++) {
        int r0 = rowBase + wm * 32 + mi * 16 + (lane >> 2);
#pragma unroll
        for (int ni = 0; ni < 4; ni++) {
            int c = wn * 32 + ni * 8 + 2 * (lane & 3);
            if (r0 < NN) {
                float2 st; st.x = acc[mi][ni][0]; st.y = acc[mi][ni][1];
                *(float2*)&C[(size_t)r0 * OC + c] = st;
            }
            int r1 = r0 + 8;
            if (r1 < NN) {
                float2 st; st.x = acc[mi][ni][2]; st.y = acc[mi][ni][3];
                *(float2*)&C[(size_t)r1 * OC + c] = st;
            }
        }
    }
}

// ---------------- finalize: out += inv * agg2 + b2 ----------------
__global__ void finalize_kernel(const float* __restrict__ b2,
                                float* __restrict__ out) {
    int i = blockIdx.x * blockDim.x + threadIdx.x;
    if (i >= NN * (OC / 4)) return;
    int n = i / (OC / 4);
    int c4 = i % (OC / 4);
    float inv = g_cnt[n];
    float4 o = ((float4*)out)[i];
    float4 a = ((const float4*)g_agg2)[i];
    float4 b = ((const float4*)b2)[c4];
    o.x += inv * a.x + b.x;
    o.y += inv * a.y + b.y;
    o.z += inv * a.z + b.z;
    o.w += inv * a.w + b.w;
    ((float4*)out)[i] = o;
}

// ---------------- launch (two streams, capture-legal fork/join) ----------------
extern "C" void kernel_launch(void* const* d_in, const int* in_sizes, int n_in,
                              void* d_out, int out_size) {
    const float* x   = (const float*)d_in[0];
    const int*   ei  = (const int*)d_in[1];      // int32
    const float* W1l = (const float*)d_in[2];
    const float* b1  = (const float*)d_in[3];
    const float* W1r = (const float*)d_in[4];
    const float* W2l = (const float*)d_in[5];
    const float* b2  = (const float*)d_in[6];
    const float* W2r = (const float*)d_in[7];
    float* out = (float*)d_out;

    static cudaStream_t s2 = nullptr;
    static cudaEvent_t ef1, ej1, ef2, ej2;
    if (s2 == nullptr) {
        cudaStreamCreateWithFlags(&s2, cudaStreamNonBlocking);
        cudaEventCreateWithFlags(&ef1, cudaEventDisableTiming);
        cudaEventCreateWithFlags(&ej1, cudaEventDisableTiming);
        cudaEventCreateWithFlags(&ef2, cudaEventDisableTiming);
        cudaEventCreateWithFlags(&ej2, cudaEventDisableTiming);
    }

    void *p_cnt, *p_agg1, *p_agg2;
    cudaGetSymbolAddress(&p_cnt, g_cnt);
    cudaGetSymbolAddress(&p_agg1, g_agg1);
    cudaGetSymbolAddress(&p_agg2, g_agg2);
    cudaMemsetAsync(p_cnt, 0, (size_t)NN * sizeof(float));
    cudaMemsetAsync(p_agg1, 0, (size_t)NN * IN_CH * sizeof(float));
    cudaMemsetAsync(p_agg2, 0, (size_t)NN * OC * sizeof(float));

    // fork: gemm1r (x @ W1r^T + b1 -> g_h raw) on s2, overlaps scatter chain
    cudaEventRecord(ef1, 0);
    cudaStreamWaitEvent(s2, ef1, 0);
    gemm1_half<<<dim3((NN + 127) / 128, 2), 256, 0, s2>>>(x, W1r, b1, 0);
    cudaEventRecord(ej1, s2);

    // main stream: degree + scatter1
    count_kernel<<<(NE + 255) / 256, 256>>>(ei);
    inv_kernel<<<(NN + 255) / 256, 256>>>();
    scatter1_kernel<<<(NE * 32 + 255) / 256, 256>>>(ei, x);

    // join, then gemm1l (mean @ W1l^T + prev, relu); x arg unused in phase 1
    cudaStreamWaitEvent(0, ej1, 0);
    gemm1_half<<<dim3((NN + 127) / 128, 2), 256>>>(x, W1l, b1, 1);

    // fork: out_raw = h @ W2r^T on s2, overlaps gemm2l + scatter2
    cudaEventRecord(ef2, 0);
    cudaStreamWaitEvent(s2, ef2, 0);
    gemm2_half<<<(NN + 127) / 128, 256, 0, s2>>>(W2r, out, 0);
    cudaEventRecord(ej2, s2);

    // main stream: P = h @ W2l^T, scatter2
    gemm2_half<<<(NN + 127) / 128, 256>>>(W2l, out, 1);
    scatter2_kernel<<<(NE * 16 + 255) / 256, 256>>>(ei);

    // join, finalize
    cudaStreamWaitEvent(0, ej2, 0);
    finalize_kernel<<<(NN * (OC / 4) + 255) / 256, 256>>>(b2, out);
}

// round 15
// speedup vs baseline: 1.1176x; 1.1176x over previous
#include <cuda_runtime.h>
#include <cstdint>
#include <cstddef>

#define NN 100000
#define NE 640000
#define IN_CH 128
#define HID 256
#define OC 64
#define SW 40   // smem row stride in words (mod 32 == 8 -> conflict-free LDS.64 frags)

#define G1_SMEM (4 * 128 * SW * 4)              // 2 x (A 128xSW + B 128xSW) buffers
#define G2_SMEM ((2 * 128 + 2 * 64) * SW * 4)   // 2 x (A 128xSW + B 64xSW)

// ---------------- scratch ----------------
__device__ __align__(16) float g_cnt[NN];
__device__ __align__(16) float g_agg1[(size_t)NN * IN_CH];
__device__ __align__(16) float g_h[(size_t)NN * HID];
__device__ __align__(16) float g_P[(size_t)NN * OC];
__device__ __align__(16) float g_agg2[(size_t)NN * OC];

__device__ __forceinline__ int clampN(int v) {
    return ((unsigned)v < (unsigned)NN) ? v : 0;
}

// ---------------- tf32 helpers ----------------
__device__ __forceinline__ unsigned cvt_tf32(float f) {
    unsigned r;
    asm("cvt.rna.tf32.f32 %0, %1;" : "=r"(r) : "f"(f));
    return r;
}
__device__ __forceinline__ void mma_tf32(float* c, const unsigned* a, const unsigned* b) {
    asm volatile(
        "mma.sync.aligned.m16n8k8.row.col.f32.tf32.tf32.f32 "
        "{%0,%1,%2,%3}, {%4,%5,%6,%7}, {%8,%9}, {%0,%1,%2,%3};"
        : "+f"(c[0]), "+f"(c[1]), "+f"(c[2]), "+f"(c[3])
        : "r"(a[0]), "r"(a[1]), "r"(a[2]), "r"(a[3]), "r"(b[0]), "r"(b[1]));
}

// pair-packed store: within each 8-k group order {v0,v4,v1,v5,v2,v6,v3,v7}
// so fragment pair (k, k+4) is one 8-byte word -> LDS.64 fragment loads.
__device__ __forceinline__ void store_packed16(unsigned* rowptr, int lc,
                                               const float4* v4, float s) {
    unsigned t[16];
#pragma unroll
    for (int i = 0; i < 4; i++) {
        t[i * 4 + 0] = cvt_tf32(v4[i].x * s);
        t[i * 4 + 1] = cvt_tf32(v4[i].y * s);
        t[i * 4 + 2] = cvt_tf32(v4[i].z * s);
        t[i * 4 + 3] = cvt_tf32(v4[i].w * s);
    }
#pragma unroll
    for (int g = 0; g < 2; g++) {
        const unsigned* u = t + g * 8;
        uint4 w0 = make_uint4(u[0], u[4], u[1], u[5]);
        uint4 w1 = make_uint4(u[2], u[6], u[3], u[7]);
        *(uint4*)(rowptr + lc + g * 8)     = w0;
        *(uint4*)(rowptr + lc + g * 8 + 4) = w1;
    }
}

// ---------------- degree count + inverse ----------------
__global__ void count_kernel(const int* __restrict__ ei) {
    int e = blockIdx.x * blockDim.x + threadIdx.x;
    if (e < NE) atomicAdd(&g_cnt[clampN(ei[NE + e])], 1.0f);
}
__global__ void inv_kernel() {
    int i = blockIdx.x * blockDim.x + threadIdx.x;
    if (i < NN) g_cnt[i] = 1.0f / fmaxf(g_cnt[i], 1.0f);
}

// ---------------- scatters (vector RED) ----------------
__global__ void scatter1_kernel(const int* __restrict__ ei,
                                const float* __restrict__ x) {
    constexpr int Q = IN_CH / 4;
    int gt = blockIdx.x * blockDim.x + threadIdx.x;
    int e = gt >> 5;
    int q = gt & 31;
    if (e >= NE) return;
    int s = clampN(ei[e]);
    int d = clampN(ei[NE + e]);
    float4 v = *((const float4*)x + (size_t)s * Q + q);
    atomicAdd((float4*)g_agg1 + (size_t)d * Q + q, v);
}
__global__ void scatter2_kernel(const int* __restrict__ ei) {
    constexpr int Q = OC / 4;
    int gt = blockIdx.x * blockDim.x + threadIdx.x;
    int e = gt >> 4;
    int q = gt & 15;
    if (e >= NE) return;
    int s = clampN(ei[e]);
    int d = clampN(ei[NE + e]);
    float4 v = *((const float4*)g_P + (size_t)s * Q + q);
    atomicAdd((float4*)g_agg2 + (size_t)d * Q + q, v);
}

// ---------------- layer-1 tf32 GEMM, ping-pong double buffer ----------------
// h[n,c] = relu( mean[n,:].W1l[c,:] + x[n,:].W1r[c,:] + b1[c] );  concat-K=256.
// BM=128, BN=128 (grid.y=2), BK=32. 8 warps 4x2; warp tile 32x64.
// One __syncthreads per kt; tile kt -> buffer kt&1 (2-buffer hazard-free).
__global__ void __launch_bounds__(256, 2)
gemm1_tf32(const float* __restrict__ x,
           const float* __restrict__ W1l,
           const float* __restrict__ W1r,
           const float* __restrict__ b1) {
    extern __shared__ __align__(16) unsigned sm1[];
    // layout: A buffers [0, 2*128*SW), B buffers [2*128*SW, 4*128*SW)

    const int tid = threadIdx.x;
    const int lane = tid & 31;
    const int warp = tid >> 5;
    const int wm = warp >> 1;
    const int wn = warp & 1;
    const int rowBase = blockIdx.x * 128;
    const int colBase = blockIdx.y * 128;

    const int lr = tid >> 1;
    const int lc = (tid & 1) * 16;

    int nA = rowBase + lr; if (nA >= NN) nA = NN - 1;
    const float scale0 = g_cnt[nA];

    float acc[2][8][4];
#pragma unroll
    for (int mi = 0; mi < 2; mi++)
#pragma unroll
        for (int ni = 0; ni < 8; ni++)
#pragma unroll
            for (int t = 0; t < 4; t++) acc[mi][ni][t] = 0.0f;

#pragma unroll 1
    for (int kt = 0; kt < 8; kt++) {
        const int p = kt & 1;
        unsigned* Asb = sm1 + p * (128 * SW);
        unsigned* Bsb = sm1 + 2 * (128 * SW) + p * (128 * SW);

        const bool first = kt < 4;
        const int koff = first ? kt * 32 : kt * 32 - 128;
        const float* ap = (first ? g_agg1 : x) + (size_t)nA * IN_CH + koff + lc;
        const float* bp = (first ? W1l : W1r) + (size_t)(colBase + lr) * IN_CH + koff + lc;
        const float s = first ? scale0 : 1.0f;

        float4 va[4], vb[4];
#pragma unroll
        for (int i = 0; i < 4; i++) va[i] = *(const float4*)(ap + i * 4);
#pragma unroll
        for (int i = 0; i < 4; i++) vb[i] = *(const float4*)(bp + i * 4);
        store_packed16(Asb + lr * SW, lc, va, s);
        store_packed16(Bsb + lr * SW, lc, vb, 1.0f);
        __syncthreads();

#pragma unroll
        for (int kk = 0; kk < 4; kk++) {
            const int kc2 = kk * 8 + (lane & 3) * 2;
            unsigned a[2][4];
#pragma unroll
            for (int mi = 0; mi < 2; mi++) {
                int r0 = wm * 32 + mi * 16 + (lane >> 2);
                uint2 lo = *(const uint2*)&Asb[r0 * SW + kc2];
                uint2 hi = *(const uint2*)&Asb[(r0 + 8) * SW + kc2];
                a[mi][0] = lo.x; a[mi][1] = hi.x; a[mi][2] = lo.y; a[mi][3] = hi.y;
            }
            unsigned bf[8][2];
#pragma unroll
            for (int ni = 0; ni < 8; ni++) {
                int c0 = wn * 64 + ni * 8 + (lane >> 2);
                uint2 bb = *(const uint2*)&Bsb[c0 * SW + kc2];
                bf[ni][0] = bb.x; bf[ni][1] = bb.y;
            }
#pragma unroll
            for (int mi = 0; mi < 2; mi++)
#pragma unroll
                for (int ni = 0; ni < 8; ni++)
                    mma_tf32(acc[mi][ni], a[mi], bf[ni]);
        }
        // no trailing sync: next iteration writes the other buffer; the next
        // sync orders those writes after every warp's reads of this buffer.
    }

#pragma unroll
    for (int mi = 0; mi < 2; mi++) {
        int r0 = rowBase + wm * 32 + mi * 16 + (lane >> 2);
#pragma unroll
        for (int ni = 0; ni < 8; ni++) {
            int c = colBase + wn * 64 + ni * 8 + 2 * (lane & 3);
            float bb0 = b1[c], bb1 = b1[c + 1];
            if (r0 < NN) {
                float2 st;
                st.x = fmaxf(acc[mi][ni][0] + bb0, 0.0f);
                st.y = fmaxf(acc[mi][ni][1] + bb1, 0.0f);
                *(float2*)&g_h[(size_t)r0 * HID + c] = st;
            }
            int r1 = r0 + 8;
            if (r1 < NN) {
                float2 st;
                st.x = fmaxf(acc[mi][ni][2] + bb0, 0.0f);
                st.y = fmaxf(acc[mi][ni][3] + bb1, 0.0f);
                *(float2*)&g_h[(size_t)r1 * HID + c] = st;
            }
        }
    }
}

// ---------------- layer-2 tf32 GEMMs, ping-pong double buffer ----------------
// blockIdx.y==0: W2l -> g_P ; ==1: W2r -> out (raw).
// BM=128, BN=64, BK=32. 8 warps 4x2; warp tile 32x32.
__global__ void __launch_bounds__(256, 2)
gemm2_tf32(const float* __restrict__ W2l,
           const float* __restrict__ W2r,
           float* __restrict__ outRaw) {
    extern __shared__ __align__(16) unsigned sm2[];
    // layout: A buffers [0, 2*128*SW), B buffers [2*128*SW, 2*128*SW + 2*64*SW)

    const float* W = (blockIdx.y == 0) ? W2l : W2r;
    float* C = (blockIdx.y == 0) ? g_P : outRaw;

    const int tid = threadIdx.x;
    const int lane = tid & 31;
    const int warp = tid >> 5;
    const int wm = warp >> 1;
    const int wn = warp & 1;
    const int rowBase = blockIdx.x * 128;

    const int lr = tid >> 1;
    const int lc = (tid & 1) * 16;
    const int br = tid >> 2;
    const int bc = (tid & 3) * 8;

    int nA = rowBase + lr; if (nA >= NN) nA = NN - 1;

    float acc[2][4][4];
#pragma unroll
    for (int mi = 0; mi < 2; mi++)
#pragma unroll
        for (int ni = 0; ni < 4; ni++)
#pragma unroll
            for (int t = 0; t < 4; t++) acc[mi][ni][t] = 0.0f;

#pragma unroll 1
    for (int kt = 0; kt < 8; kt++) {
        const int p = kt & 1;
        unsigned* Asb = sm2 + p * (128 * SW);
        unsigned* Bsb = sm2 + 2 * (128 * SW) + p * (64 * SW);

        const int koff = kt * 32;
        const float* ap = g_h + (size_t)nA * HID + koff + lc;
        float4 va[4];
#pragma unroll
        for (int i = 0; i < 4; i++) va[i] = *(const float4*)(ap + i * 4);
        store_packed16(Asb + lr * SW, lc, va, 1.0f);
        {
            const float* bp = W + (size_t)br * HID + koff + bc;
            float4 v0 = *(const float4*)(bp);
            float4 v1 = *(const float4*)(bp + 4);
            unsigned u[8];
            u[0] = cvt_tf32(v0.x); u[1] = cvt_tf32(v0.y);
            u[2] = cvt_tf32(v0.z); u[3] = cvt_tf32(v0.w);
            u[4] = cvt_tf32(v1.x); u[5] = cvt_tf32(v1.y);
            u[6] = cvt_tf32(v1.z); u[7] = cvt_tf32(v1.w);
            uint4 w0 = make_uint4(u[0], u[4], u[1], u[5]);
            uint4 w1 = make_uint4(u[2], u[6], u[3], u[7]);
            *(uint4*)(Bsb + br * SW + bc)     = w0;
            *(uint4*)(Bsb + br * SW + bc + 4) = w1;
        }
        __syncthreads();

#pragma unroll
        for (int kk = 0; kk < 4; kk++) {
            const int kc2 = kk * 8 + (lane & 3) * 2;
            unsigned a[2][4];
#pragma unroll
            for (int mi = 0; mi < 2; mi++) {
                int r0 = wm * 32 + mi * 16 + (lane >> 2);
                uint2 lo = *(const uint2*)&Asb[r0 * SW + kc2];
                uint2 hi = *(const uint2*)&Asb[(r0 + 8) * SW + kc2];
                a[mi][0] = lo.x; a[mi][1] = hi.x; a[mi][2] = lo.y; a[mi][3] = hi.y;
            }
            unsigned bf[4][2];
#pragma unroll
            for (int ni = 0; ni < 4; ni++) {
                int c0 = wn * 32 + ni * 8 + (lane >> 2);
                uint2 bb = *(const uint2*)&Bsb[c0 * SW + kc2];
                bf[ni][0] = bb.x; bf[ni][1] = bb.y;
            }
#pragma unroll
            for (int mi = 0; mi < 2; mi++)
#pragma unroll
                for (int ni = 0; ni < 4; ni++)
                    mma_tf32(acc[mi][ni], a[mi], bf[ni]);
        }
    }

#pragma unroll
    for (int mi = 0; mi < 2; mi++) {
        int r0 = rowBase + wm * 32 + mi * 16 + (lane >> 2);
#pragma unroll
        for (int ni = 0; ni < 4; ni++) {
            int c = wn * 32 + ni * 8 + 2 * (lane & 3);
            if (r0 < NN) {
                float2 st; st.x = acc[mi][ni][0]; st.y = acc[mi][ni][1];
                *(float2*)&C[(size_t)r0 * OC + c] = st;
            }
            int r1 = r0 + 8;
            if (r1 < NN) {
                float2 st; st.x = acc[mi][ni][2]; st.y = acc[mi][ni][3];
                *(float2*)&C[(size_t)r1 * OC + c] = st;
            }
        }
    }
}

// ---------------- finalize: out += inv * agg2 + b2 ----------------
__global__ void finalize_kernel(const float* __restrict__ b2,
                                float* __restrict__ out) {
    int i = blockIdx.x * blockDim.x + threadIdx.x;
    if (i >= NN * (OC / 4)) return;
    int n = i / (OC / 4);
    int c4 = i % (OC / 4);
    float inv = g_cnt[n];
    float4 o = ((float4*)out)[i];
    float4 a = ((const float4*)g_agg2)[i];
    float4 b = ((const float4*)b2)[c4];
    o.x += inv * a.x + b.x;
    o.y += inv * a.y + b.y;
    o.z += inv * a.z + b.z;
    o.w += inv * a.w + b.w;
    ((float4*)out)[i] = o;
}

// ---------------- launch (single stream) ----------------
extern "C" void kernel_launch(void* const* d_in, const int* in_sizes, int n_in,
                              void* d_out, int out_size) {
    const float* x   = (const float*)d_in[0];
    const int*   ei  = (const int*)d_in[1];      // int32
    const float* W1l = (const float*)d_in[2];
    const float* b1  = (const float*)d_in[3];
    const float* W1r = (const float*)d_in[4];
    const float* W2l = (const float*)d_in[5];
    const float* b2  = (const float*)d_in[6];
    const float* W2r = (const float*)d_in[7];
    float* out = (float*)d_out;

    static bool attrDone = false;
    if (!attrDone) {
        cudaFuncSetAttribute(gemm1_tf32, cudaFuncAttributeMaxDynamicSharedMemorySize, G1_SMEM);
        cudaFuncSetAttribute(gemm2_tf32, cudaFuncAttributeMaxDynamicSharedMemorySize, G2_SMEM);
        attrDone = true;
    }

    void *p_cnt, *p_agg1, *p_agg2;
    cudaGetSymbolAddress(&p_cnt, g_cnt);
    cudaGetSymbolAddress(&p_agg1, g_agg1);
    cudaGetSymbolAddress(&p_agg2, g_agg2);
    cudaMemsetAsync(p_cnt, 0, (size_t)NN * sizeof(float));
    cudaMemsetAsync(p_agg1, 0, (size_t)NN * IN_CH * sizeof(float));
    cudaMemsetAsync(p_agg2, 0, (size_t)NN * OC * sizeof(float));

    count_kernel<<<(NE + 255) / 256, 256>>>(ei);
    inv_kernel<<<(NN + 255) / 256, 256>>>();

    scatter1_kernel<<<(NE * 32 + 255) / 256, 256>>>(ei, x);

    gemm1_tf32<<<dim3((NN + 127) / 128, 2), 256, G1_SMEM>>>(x, W1l, W1r, b1);

    gemm2_tf32<<<dim3((NN + 127) / 128, 2), 256, G2_SMEM>>>(W2l, W2r, out);

    scatter2_kernel<<<(NE * 16 + 255) / 256, 256>>>(ei);

    finalize_kernel<<<(NN * (OC / 4) + 255) / 256, 256>>>(b2, out);
}

// round 17
// speedup vs baseline: 1.1564x; 1.0347x over previous
#include <cuda_runtime.h>
#include <cstdint>
#include <cstddef>

#define NN 100000
#define NE 640000
#define IN_CH 128
#define HID 256
#define OC 64
#define SW 40   // smem row stride in words (mod 32 == 8 -> conflict-free LDS.64 frags)

#define G1_SMEM (4 * 128 * SW * 4)   // 2 x (A 128xSW + B 128xSW) ping-pong buffers

// ---------------- scratch ----------------
__device__ __align__(16) float g_cnt[NN];                  // raw in-degree (float)
__device__ __align__(16) float g_agg1[(size_t)NN * IN_CH];
__device__ __align__(16) float g_h[(size_t)NN * HID];
__device__ __align__(16) float g_P[(size_t)NN * OC];
__device__ __align__(16) float g_agg2[(size_t)NN * OC];

__device__ __forceinline__ int clampN(int v) {
    return ((unsigned)v < (unsigned)NN) ? v : 0;
}

// ---------------- tf32 helpers ----------------
__device__ __forceinline__ unsigned cvt_tf32(float f) {
    unsigned r;
    asm("cvt.rna.tf32.f32 %0, %1;" : "=r"(r) : "f"(f));
    return r;
}
__device__ __forceinline__ void mma_tf32(float* c, const unsigned* a, const unsigned* b) {
    asm volatile(
        "mma.sync.aligned.m16n8k8.row.col.f32.tf32.tf32.f32 "
        "{%0,%1,%2,%3}, {%4,%5,%6,%7}, {%8,%9}, {%0,%1,%2,%3};"
        : "+f"(c[0]), "+f"(c[1]), "+f"(c[2]), "+f"(c[3])
        : "r"(a[0]), "r"(a[1]), "r"(a[2]), "r"(a[3]), "r"(b[0]), "r"(b[1]));
}

// pair-packed store: within each 8-k group order {v0,v4,v1,v5,v2,v6,v3,v7}
// so fragment pair (k, k+4) is one 8-byte word -> LDS.64 fragment loads.
__device__ __forceinline__ void store_packed16(unsigned* rowptr, int lc,
                                               const float4* v4, float s) {
    unsigned t[16];
#pragma unroll
    for (int i = 0; i < 4; i++) {
        t[i * 4 + 0] = cvt_tf32(v4[i].x * s);
        t[i * 4 + 1] = cvt_tf32(v4[i].y * s);
        t[i * 4 + 2] = cvt_tf32(v4[i].z * s);
        t[i * 4 + 3] = cvt_tf32(v4[i].w * s);
    }
#pragma unroll
    for (int g = 0; g < 2; g++) {
        const unsigned* u = t + g * 8;
        uint4 w0 = make_uint4(u[0], u[4], u[1], u[5]);
        uint4 w1 = make_uint4(u[2], u[6], u[3], u[7]);
        *(uint4*)(rowptr + lc + g * 8)     = w0;
        *(uint4*)(rowptr + lc + g * 8 + 4) = w1;
    }
}

// ---------------- scatter1 + degree count fused ----------------
// agg1[dst] += x[src] (float4 RED); q==0 lane also counts the edge.
__global__ void scatter1_kernel(const int* __restrict__ ei,
                                const float* __restrict__ x) {
    constexpr int Q = IN_CH / 4;
    int gt = blockIdx.x * blockDim.x + threadIdx.x;
    int e = gt >> 5;
    int q = gt & 31;
    if (e >= NE) return;
    int s = clampN(ei[e]);
    int d = clampN(ei[NE + e]);
    if (q == 0) atomicAdd(&g_cnt[d], 1.0f);
    float4 v = *((const float4*)x + (size_t)s * Q + q);
    atomicAdd((float4*)g_agg1 + (size_t)d * Q + q, v);
}
__global__ void scatter2_kernel(const int* __restrict__ ei) {
    constexpr int Q = OC / 4;
    int gt = blockIdx.x * blockDim.x + threadIdx.x;
    int e = gt >> 4;
    int q = gt & 15;
    if (e >= NE) return;
    int s = clampN(ei[e]);
    int d = clampN(ei[NE + e]);
    float4 v = *((const float4*)g_P + (size_t)s * Q + q);
    atomicAdd((float4*)g_agg2 + (size_t)d * Q + q, v);
}

// ---------------- layer-1 tf32 GEMM, ping-pong double buffer ----------------
// h[n,c] = relu( mean[n,:].W1l[c,:] + x[n,:].W1r[c,:] + b1[c] );  concat-K=256.
// BM=128, BN=128 (grid.y=2), BK=32. 8 warps 4x2; warp tile 32x64.
__global__ void __launch_bounds__(256, 2)
gemm1_tf32(const float* __restrict__ x,
           const float* __restrict__ W1l,
           const float* __restrict__ W1r,
           const float* __restrict__ b1) {
    extern __shared__ __align__(16) unsigned sm1[];

    const int tid = threadIdx.x;
    const int lane = tid & 31;
    const int warp = tid >> 5;
    const int wm = warp >> 1;
    const int wn = warp & 1;
    const int rowBase = blockIdx.x * 128;
    const int colBase = blockIdx.y * 128;

    const int lr = tid >> 1;
    const int lc = (tid & 1) * 16;

    int nA = rowBase + lr; if (nA >= NN) nA = NN - 1;
    const float scale0 = 1.0f / fmaxf(g_cnt[nA], 1.0f);   // raw count -> inverse

    float acc[2][8][4];
#pragma unroll
    for (int mi = 0; mi < 2; mi++)
#pragma unroll
        for (int ni = 0; ni < 8; ni++)
#pragma unroll
            for (int t = 0; t < 4; t++) acc[mi][ni][t] = 0.0f;

#pragma unroll 1
    for (int kt = 0; kt < 8; kt++) {
        const int p = kt & 1;
        unsigned* Asb = sm1 + p * (128 * SW);
        unsigned* Bsb = sm1 + 2 * (128 * SW) + p * (128 * SW);

        const bool first = kt < 4;
        const int koff = first ? kt * 32 : kt * 32 - 128;
        const float* ap = (first ? g_agg1 : x) + (size_t)nA * IN_CH + koff + lc;
        const float* bp = (first ? W1l : W1r) + (size_t)(colBase + lr) * IN_CH + koff + lc;
        const float s = first ? scale0 : 1.0f;

        float4 va[4], vb[4];
#pragma unroll
        for (int i = 0; i < 4; i++) va[i] = *(const float4*)(ap + i * 4);
#pragma unroll
        for (int i = 0; i < 4; i++) vb[i] = *(const float4*)(bp + i * 4);
        store_packed16(Asb + lr * SW, lc, va, s);
        store_packed16(Bsb + lr * SW, lc, vb, 1.0f);
        __syncthreads();

#pragma unroll
        for (int kk = 0; kk < 4; kk++) {
            const int kc2 = kk * 8 + (lane & 3) * 2;
            unsigned a[2][4];
#pragma unroll
            for (int mi = 0; mi < 2; mi++) {
                int r0 = wm * 32 + mi * 16 + (lane >> 2);
                uint2 lo = *(const uint2*)&Asb[r0 * SW + kc2];
                uint2 hi = *(const uint2*)&Asb[(r0 + 8) * SW + kc2];
                a[mi][0] = lo.x; a[mi][1] = hi.x; a[mi][2] = lo.y; a[mi][3] = hi.y;
            }
            unsigned bf[8][2];
#pragma unroll
            for (int ni = 0; ni < 8; ni++) {
                int c0 = wn * 64 + ni * 8 + (lane >> 2);
                uint2 bb = *(const uint2*)&Bsb[c0 * SW + kc2];
                bf[ni][0] = bb.x; bf[ni][1] = bb.y;
            }
#pragma unroll
            for (int mi = 0; mi < 2; mi++)
#pragma unroll
                for (int ni = 0; ni < 8; ni++)
                    mma_tf32(acc[mi][ni], a[mi], bf[ni]);
        }
    }

#pragma unroll
    for (int mi = 0; mi < 2; mi++) {
        int r0 = rowBase + wm * 32 + mi * 16 + (lane >> 2);
#pragma unroll
        for (int ni = 0; ni < 8; ni++) {
            int c = colBase + wn * 64 + ni * 8 + 2 * (lane & 3);
            float bb0 = b1[c], bb1 = b1[c + 1];
            if (r0 < NN) {
                float2 st;
                st.x = fmaxf(acc[mi][ni][0] + bb0, 0.0f);
                st.y = fmaxf(acc[mi][ni][1] + bb1, 0.0f);
                *(float2*)&g_h[(size_t)r0 * HID + c] = st;
            }
            int r1 = r0 + 8;
            if (r1 < NN) {
                float2 st;
                st.x = fmaxf(acc[mi][ni][2] + bb0, 0.0f);
                st.y = fmaxf(acc[mi][ni][3] + bb1, 0.0f);
                *(float2*)&g_h[(size_t)r1 * HID + c] = st;
            }
        }
    }
}

// ---------------- layer-2 fused GEMM: D[128n x 128c] = h @ [W2l; W2r]^T ----------------
// B rows 0-63 = W2l, rows 64-127 = W2r. D cols 0-63 -> g_P, 64-127 -> out (raw).
// Same tile scheme as gemm1 (BM=128, BN=128, BK=32, warp tile 32x64); A staged ONCE.
__global__ void __launch_bounds__(256, 2)
gemm2_tf32(const float* __restrict__ W2l,
           const float* __restrict__ W2r,
           float* __restrict__ outRaw) {
    extern __shared__ __align__(16) unsigned sm2[];

    const int tid = threadIdx.x;
    const int lane = tid & 31;
    const int warp = tid >> 5;
    const int wm = warp >> 1;
    const int wn = warp & 1;
    const int rowBase = blockIdx.x * 128;

    const int lr = tid >> 1;
    const int lc = (tid & 1) * 16;

    int nA = rowBase + lr; if (nA >= NN) nA = NN - 1;
    const float* Wrow = (lr < 64) ? (W2l + (size_t)lr * HID)
                                  : (W2r + (size_t)(lr - 64) * HID);

    float acc[2][8][4];
#pragma unroll
    for (int mi = 0; mi < 2; mi++)
#pragma unroll
        for (int ni = 0; ni < 8; ni++)
#pragma unroll
            for (int t = 0; t < 4; t++) acc[mi][ni][t] = 0.0f;

#pragma unroll 1
    for (int kt = 0; kt < 8; kt++) {
        const int p = kt & 1;
        unsigned* Asb = sm2 + p * (128 * SW);
        unsigned* Bsb = sm2 + 2 * (128 * SW) + p * (128 * SW);

        const int koff = kt * 32;
        const float* ap = g_h + (size_t)nA * HID + koff + lc;
        const float* bp = Wrow + koff + lc;

        float4 va[4], vb[4];
#pragma unroll
        for (int i = 0; i < 4; i++) va[i] = *(const float4*)(ap + i * 4);
#pragma unroll
        for (int i = 0; i < 4; i++) vb[i] = *(const float4*)(bp + i * 4);
        store_packed16(Asb + lr * SW, lc, va, 1.0f);
        store_packed16(Bsb + lr * SW, lc, vb, 1.0f);
        __syncthreads();

#pragma unroll
        for (int kk = 0; kk < 4; kk++) {
            const int kc2 = kk * 8 + (lane & 3) * 2;
            unsigned a[2][4];
#pragma unroll
            for (int mi = 0; mi < 2; mi++) {
                int r0 = wm * 32 + mi * 16 + (lane >> 2);
                uint2 lo = *(const uint2*)&Asb[r0 * SW + kc2];
                uint2 hi = *(const uint2*)&Asb[(r0 + 8) * SW + kc2];
                a[mi][0] = lo.x; a[mi][1] = hi.x; a[mi][2] = lo.y; a[mi][3] = hi.y;
            }
            unsigned bf[8][2];
#pragma unroll
            for (int ni = 0; ni < 8; ni++) {
                int c0 = wn * 64 + ni * 8 + (lane >> 2);
                uint2 bb = *(const uint2*)&Bsb[c0 * SW + kc2];
                bf[ni][0] = bb.x; bf[ni][1] = bb.y;
            }
#pragma unroll
            for (int mi = 0; mi < 2; mi++)
#pragma unroll
                for (int ni = 0; ni < 8; ni++)
                    mma_tf32(acc[mi][ni], a[mi], bf[ni]);
        }
    }

    // epilogue: wn==0 warps own D cols 0-63 (-> g_P), wn==1 own 64-127 (-> out)
    float* dstBase = wn ? outRaw : g_P;
#pragma unroll
    for (int mi = 0; mi < 2; mi++) {
        int r0 = rowBase + wm * 32 + mi * 16 + (lane >> 2);
#pragma unroll
        for (int ni = 0; ni < 8; ni++) {
            int c = ni * 8 + 2 * (lane & 3);            // 0..63 within dst
            if (r0 < NN) {
                float2 st; st.x = acc[mi][ni][0]; st.y = acc[mi][ni][1];
                *(float2*)&dstBase[(size_t)r0 * OC + c] = st;
            }
            int r1 = r0 + 8;
            if (r1 < NN) {
                float2 st; st.x = acc[mi][ni][2]; st.y = acc[mi][ni][3];
                *(float2*)&dstBase[(size_t)r1 * OC + c] = st;
            }
        }
    }
}

// ---------------- finalize: out += (1/max(cnt,1)) * agg2 + b2 ----------------
__global__ void finalize_kernel(const float* __restrict__ b2,
                                float* __restrict__ out) {
    int i = blockIdx.x * blockDim.x + threadIdx.x;
    if (i >= NN * (OC / 4)) return;
    int n = i / (OC / 4);
    int c4 = i % (OC / 4);
    float inv = 1.0f / fmaxf(g_cnt[n], 1.0f);
    float4 o = ((float4*)out)[i];
    float4 a = ((const float4*)g_agg2)[i];
    float4 b = ((const float4*)b2)[c4];
    o.x += inv * a.x + b.x;
    o.y += inv * a.y + b.y;
    o.z += inv * a.z + b.z;
    o.w += inv * a.w + b.w;
    ((float4*)out)[i] = o;
}

// ---------------- launch ----------------
extern "C" void kernel_launch(void* const* d_in, const int* in_sizes, int n_in,
                              void* d_out, int out_size) {
    const float* x   = (const float*)d_in[0];
    const int*   ei  = (const int*)d_in[1];      // int32
    const float* W1l = (const float*)d_in[2];
    const float* b1  = (const float*)d_in[3];
    const float* W1r = (const float*)d_in[4];
    const float* W2l = (const float*)d_in[5];
    const float* b2  = (const float*)d_in[6];
    const float* W2r = (const float*)d_in[7];
    float* out = (float*)d_out;

    static bool attrDone = false;
    if (!attrDone) {
        cudaFuncSetAttribute(gemm1_tf32, cudaFuncAttributeMaxDynamicSharedMemorySize, G1_SMEM);
        cudaFuncSetAttribute(gemm2_tf32, cudaFuncAttributeMaxDynamicSharedMemorySize, G1_SMEM);
        attrDone = true;
    }

    void *p_cnt, *p_agg1, *p_agg2;
    cudaGetSymbolAddress(&p_cnt, g_cnt);
    cudaGetSymbolAddress(&p_agg1, g_agg1);
    cudaGetSymbolAddress(&p_agg2, g_agg2);
    cudaMemsetAsync(p_cnt, 0, (size_t)NN * sizeof(float));
    cudaMemsetAsync(p_agg1, 0, (size_t)NN * IN_CH * sizeof(float));
    cudaMemsetAsync(p_agg2, 0, (size_t)NN * OC * sizeof(float));

    // agg1[dst] += x[src]; counts fused (q==0 lane)
    scatter1_kernel<<<(NE * 32 + 255) / 256, 256>>>(ei, x);

    // h = relu([agg1/cnt | x] @ [W1l | W1r]^T + b1)
    gemm1_tf32<<<dim3((NN + 127) / 128, 2), 256, G1_SMEM>>>(x, W1l, W1r, b1);

    // fused: P = h @ W2l^T ; out_raw = h @ W2r^T
    gemm2_tf32<<<(NN + 127) / 128, 256, G1_SMEM>>>(W2l, W2r, out);

    // agg2[dst] += P[src]
    scatter2_kernel<<<(NE * 16 + 255) / 256, 256>>>(ei);

    // out = out_raw + agg2/cnt + b2
    finalize_kernel<<<(NN * (OC / 4) + 255) / 256, 256>>>(b2, out);
}